// round 8
// baseline (speedup 1.0000x reference)
#include <cuda_runtime.h>
#include <cstdint>
#include <math.h>

#define BB 8
#define DD 1024
#define HH 16
#define HD 64
#define PAST 8192
#define NSPLIT 8
#define CHUNK (PAST / NSPLIT)   // 1024 keys per block

#define NGEMV (3 * DD)          // 3072 gemv blocks
#define NATT  (NSPLIT * HH * BB)// 1024 attention blocks

// ---------------- scratch (no allocations allowed) ----------------
__device__ float g_qkv[3 * BB * DD];               // [m][b][d] raw (pre-RoPE) q,k,v
__device__ float g_part_o[BB * HH * NSPLIT * HD];  // sum p*v per split
__device__ float g_part_l[BB * HH * NSPLIT];       // sum p per split
__device__ float g_attn[BB * DD];                  // attention output before Wo
__device__ int   g_cnt[BB * HH];                   // per-(b,h) split counter (self-reset)
__device__ int   g_qcnt[HH];                       // q rows ready per head (0..64)
__device__ int   g_kvcnt[HH];                      // k+v rows ready per head (0..128)
__device__ int   g_done;                           // combines finished (0..128)

__device__ __forceinline__ void cp_async16(uint32_t saddr, const void* gaddr) {
    asm volatile("cp.async.cg.shared.global [%0], [%1], 16;" :: "r"(saddr), "l"(gaddr));
}

// ================= fused kernel: QKV GEMV blocks + flash-decode blocks =======
__global__ void __launch_bounds__(256) fused_qkv_attn(
        const float* __restrict__ x,
        const float* __restrict__ Wq, const float* __restrict__ bq,
        const float* __restrict__ Wk, const float* __restrict__ bk,
        const float* __restrict__ Wv, const float* __restrict__ bv,
        const float* __restrict__ pk, const float* __restrict__ pv) {
    __shared__ float smem_buf[1152];
    __shared__ int   sflag;
    const int bid = blockIdx.x;
    const int t   = threadIdx.x;

    if (bid < NGEMV) {
        // ---------------- GEMV block: one row of [Wq;Wk;Wv] for all 8 batches
        const int m = bid >> 10;
        const int r = bid & 1023;
        const float* W    = (m == 0) ? Wq : (m == 1) ? Wk : Wv;
        const float* bias = (m == 0) ? bq : (m == 1) ? bk : bv;

        // stage weight row (4 KB) into smem via cp.async (one float4/thread)
        float* sw = smem_buf;
        {
            uint32_t sb = (uint32_t)__cvta_generic_to_shared(sw);
            cp_async16(sb + t * 16, (const float4*)(W + (size_t)r * DD) + t);
            asm volatile("cp.async.commit_group;");
        }

        // thread layout: 4 column-groups x 64 col-threads; each group owns 2 batches
        const int grp = t >> 6;          // 0..3
        const int c   = t & 63;          // 0..63 (16 columns each -> 4 float4)
        const int b0  = grp * 2, b1 = b0 + 1;

        // x loads overlap the cp.async wait
        const float4* __restrict__ x4 = (const float4*)x;
        float4 xa[4], xb[4];
#pragma unroll
        for (int j = 0; j < 4; j++) {
            xa[j] = __ldg(x4 + b0 * (DD / 4) + c + 64 * j);
            xb[j] = __ldg(x4 + b1 * (DD / 4) + c + 64 * j);
        }

        asm volatile("cp.async.wait_group 0;");
        __syncthreads();

        const float4* __restrict__ sw4 = (const float4*)sw;
        float a0 = 0.f, a1 = 0.f;
#pragma unroll
        for (int j = 0; j < 4; j++) {
            float4 w4 = sw4[c + 64 * j];
            a0 += w4.x * xa[j].x + w4.y * xa[j].y + w4.z * xa[j].z + w4.w * xa[j].w;
            a1 += w4.x * xb[j].x + w4.y * xb[j].y + w4.z * xb[j].z + w4.w * xb[j].w;
        }
#pragma unroll
        for (int off = 16; off > 0; off >>= 1) {
            a0 += __shfl_xor_sync(0xffffffffu, a0, off);
            a1 += __shfl_xor_sync(0xffffffffu, a1, off);
        }

        float* red = smem_buf + 1024;    // 16 floats [warp][2]
        const int warp = t >> 5, lane = t & 31;
        if (lane == 0) { red[warp * 2] = a0; red[warp * 2 + 1] = a1; }
        __syncthreads();

        if (t < BB) {                    // t = batch
            const int g2 = t >> 1, o = t & 1;
            float s = red[(g2 * 2) * 2 + o] + red[(g2 * 2 + 1) * 2 + o];
            g_qkv[m * BB * DD + t * DD + r] = s + bias[r];
        }
        __threadfence();
        __syncthreads();
        if (t == 0) {
            if (m == 0) atomicAdd(&g_qcnt[r >> 6], 1);
            else        atomicAdd(&g_kvcnt[r >> 6], 1);
        }
        return;
    }

    // ---------------- attention block ----------------
    const int idx   = bid - NGEMV;
    const int split = idx & (NSPLIT - 1);
    const int h     = (idx >> 3) & (HH - 1);
    const int b     = idx >> 7;
    const int bh    = b * HH + h;
    const int l16   = t & 15;
    const int hw    = t >> 4;

    // smem carve
    float* sm_o   = smem_buf;            // 16*64
    float* sm_l   = smem_buf + 1024;     // 16
    float* s_cos  = smem_buf + 1040;     // 32
    float* s_sin  = smem_buf + 1072;     // 32
    float* sm_red = smem_buf + 1104;     // 2
    float* sm_sn  = smem_buf + 1106;     // 1

    // RoPE table (DP angles), hidden under the q spin
    if (t < HD / 2) {
        double inv = pow(10000.0, -(double)t / (HD / 2));
        double ang = (double)PAST * inv;
        s_cos[t] = (float)cos(ang);
        s_sin[t] = (float)sin(ang);
    }
    if (t == 0) {
        while (((volatile int*)g_qcnt)[h] < HD) __nanosleep(100);
        __threadfence();
    }
    __syncthreads();

    // q load + RoPE on the fly
    float4 qr = ((const float4*)(g_qkv + b * DD + h * HD))[l16];
    float4 qp;
    qp.x = __shfl_xor_sync(0xffffffffu, qr.x, 8);
    qp.y = __shfl_xor_sync(0xffffffffu, qr.y, 8);
    qp.z = __shfl_xor_sync(0xffffffffu, qr.z, 8);
    qp.w = __shfl_xor_sync(0xffffffffu, qr.w, 8);
    {
        int j0 = 4 * l16;
        bool lo = (l16 < 8);
        int i0 = lo ? j0 : j0 - 32;
        float sgn = lo ? -1.f : 1.f;
        qr.x = qr.x * s_cos[i0 + 0] + sgn * qp.x * s_sin[i0 + 0];
        qr.y = qr.y * s_cos[i0 + 1] + sgn * qp.y * s_sin[i0 + 1];
        qr.z = qr.z * s_cos[i0 + 2] + sgn * qp.z * s_sin[i0 + 2];
        qr.w = qr.w * s_cos[i0 + 3] + sgn * qp.w * s_sin[i0 + 3];
    }

    const long base = (long)bh * PAST * (HD / 4);
    const float4* __restrict__ K4 = (const float4*)pk + base;
    const float4* __restrict__ V4 = (const float4*)pv + base;

    float l = 0.f;
    float4 acc = make_float4(0.f, 0.f, 0.f, 0.f);

    const int t0 = split * CHUNK;
#pragma unroll 4
    for (int it = 0; it < CHUNK / 16; it++) {
        const int tt = t0 + it * 16 + hw;
        float4 kk = __ldcs(K4 + tt * 16 + l16);
        float4 vv = __ldcs(V4 + tt * 16 + l16);
        float s = kk.x * qr.x + kk.y * qr.y + kk.z * qr.z + kk.w * qr.w;
        s += __shfl_xor_sync(0xffffffffu, s, 8);
        s += __shfl_xor_sync(0xffffffffu, s, 4);
        s += __shfl_xor_sync(0xffffffffu, s, 2);
        s += __shfl_xor_sync(0xffffffffu, s, 1);
        float p = __expf(s * 0.125f);    // 1/sqrt(64); bounded scores, no max needed
        l += p;
        acc.x += p * vv.x;
        acc.y += p * vv.y;
        acc.z += p * vv.z;
        acc.w += p * vv.w;
    }

    // block-level combine of 16 half-warps
    if (l16 == 0) sm_l[hw] = l;
    ((float4*)(sm_o + hw * HD))[l16] = acc;
    __syncthreads();

    const int pidx = bh * NSPLIT + split;
    if (t < HD) {
        float num = 0.f;
#pragma unroll
        for (int i = 0; i < 16; i++) num += sm_o[i * HD + t];
        g_part_o[pidx * HD + t] = num;
    }
    if (t == 0) {
        float den = 0.f;
#pragma unroll
        for (int i = 0; i < 16; i++) den += sm_l[i];
        g_part_l[pidx] = den;
    }

    __threadfence();
    __syncthreads();
    if (t == 0) sflag = (atomicAdd(&g_cnt[bh], 1) == NSPLIT - 1);
    __syncthreads();
    if (!sflag) return;
    if (t == 0) {
        g_cnt[bh] = 0;                   // self-reset for next replay
        while (((volatile int*)g_kvcnt)[h] < 2 * HD) __nanosleep(100);
        __threadfence();
    }
    __syncthreads();

    if (t < HD) {
        const float* q = g_qkv + b * DD + h * HD;
        const float* k = g_qkv + BB * DD + b * DD + h * HD;
        float qv, kv;
        if (t < 32) {
            float c = s_cos[t], s = s_sin[t];
            qv = q[t] * c - q[t + 32] * s;
            kv = k[t] * c - k[t + 32] * s;
        } else {
            float c = s_cos[t - 32], s = s_sin[t - 32];
            qv = q[t] * c + q[t - 32] * s;
            kv = k[t] * c + k[t - 32] * s;
        }
        float prod = qv * kv;
#pragma unroll
        for (int off = 16; off > 0; off >>= 1)
            prod += __shfl_xor_sync(0xffffffffu, prod, off);
        if ((t & 31) == 0) sm_red[t >> 5] = prod;
    }
    __syncthreads();
    if (t == 0) sm_sn[0] = (sm_red[0] + sm_red[1]) * 0.125f;
    __syncthreads();

    if (t < HD) {
        const float wn = __expf(sm_sn[0]);
        const float* vn = g_qkv + 2 * BB * DD + b * DD + h * HD;
        float num = wn * vn[t];
        float den = wn;
        const int pb = bh * NSPLIT;
#pragma unroll
        for (int i = 0; i < NSPLIT; i++) {
            num += g_part_o[(pb + i) * HD + t];
            den += g_part_l[pb + i];
        }
        g_attn[b * DD + h * HD + t] = num / den;
    }
    __threadfence();
    __syncthreads();
    if (t == 0) {
        int d = atomicAdd(&g_done, 1);
        if (d == BB * HH - 1) {          // last combine resets all counters
#pragma unroll
            for (int i = 0; i < HH; i++) { g_qcnt[i] = 0; g_kvcnt[i] = 0; }
            g_done = 0;
        }
    }
}

// ---------------- kernel 2: output projection (one row per block) ----------------
__global__ void __launch_bounds__(256) out_gemv(
        const float* __restrict__ Wo, const float* __restrict__ bo,
        float* __restrict__ out) {
    const int r = blockIdx.x;
    const int t = threadIdx.x;
    const int warp = t >> 5, lane = t & 31;

    const float4 w = ((const float4*)(Wo + (size_t)r * DD))[t];
    const float4* __restrict__ a4 = (const float4*)g_attn;

    float acc[BB];
#pragma unroll
    for (int b = 0; b < BB; b++) {
        float4 xv = __ldg(a4 + b * (DD / 4) + t);
        acc[b] = w.x * xv.x + w.y * xv.y + w.z * xv.z + w.w * xv.w;
    }
#pragma unroll
    for (int off = 16; off > 0; off >>= 1)
#pragma unroll
        for (int b = 0; b < BB; b++)
            acc[b] += __shfl_xor_sync(0xffffffffu, acc[b], off);

    __shared__ float sm[8][BB];
    if (lane == 0) {
#pragma unroll
        for (int b = 0; b < BB; b++) sm[warp][b] = acc[b];
    }
    __syncthreads();

    if (t < BB) {
        float s = 0.f;
#pragma unroll
        for (int wi = 0; wi < 8; wi++) s += sm[wi][t];
        out[t * DD + r] = s + bo[r];
    }
}

// ---------------- launcher ----------------
extern "C" void kernel_launch(void* const* d_in, const int* in_sizes, int n_in,
                              void* d_out, int out_size) {
    const float* x      = (const float*)d_in[0];
    const float* Wq     = (const float*)d_in[1];
    const float* bq     = (const float*)d_in[2];
    const float* Wk     = (const float*)d_in[3];
    const float* bk     = (const float*)d_in[4];
    const float* Wv     = (const float*)d_in[5];
    const float* bv     = (const float*)d_in[6];
    const float* Wo     = (const float*)d_in[7];
    const float* bo     = (const float*)d_in[8];
    const float* past_k = (const float*)d_in[9];
    const float* past_v = (const float*)d_in[10];
    float* out = (float*)d_out;

    fused_qkv_attn<<<NGEMV + NATT, 256>>>(x, Wq, bq, Wk, bk, Wv, bv, past_k, past_v);
    out_gemv<<<DD, 256>>>(Wo, bo, out);
}